// round 2
// baseline (speedup 1.0000x reference)
#include <cuda_runtime.h>

#define NB 2
#define NT 2048
#define NC 512
#define NH 16
#define ND 32
#define BT (NB*NT)          // 4096
#define SCALE 0.17677669529663687f   // 1/sqrt(32)

// Scratch (device globals: allocation-free)
__device__ float g_q[NB*NH*NT*ND];
__device__ float g_k[NB*NH*NT*ND];
__device__ float g_v[NB*NH*NT*ND];
__device__ float g_o[NB*NH*NT*ND];
__device__ float g_m[NB*NH*NT];
__device__ float g_l[NB*NH*NT];

// ---------------------------------------------------------------------------
// QKV projection: y[m][n] = sum_c x[m][c]*W[n][c] + bias[n], scattered to
// (B,H,T,D). sel: 0->g_q, 1->g_k, 2->g_v.
// Grid (BT/64, NC/64), 256 threads, BM=BN=64, BK=16, 4x4 microtile.
// ---------------------------------------------------------------------------
__global__ __launch_bounds__(256) void gemm_qkv(const float* __restrict__ x,
                                                const float* __restrict__ W,
                                                const float* __restrict__ bias,
                                                int sel) {
    __shared__ float As[16][65];
    __shared__ float Bs[16][65];
    float* outp = (sel == 0) ? g_q : (sel == 1) ? g_k : g_v;

    int m0 = blockIdx.x * 64;
    int n0 = blockIdx.y * 64;
    int tid = threadIdx.x;
    int tx = tid & 15, ty = tid >> 4;
    int lm = tid >> 2;            // 0..63
    int lk = (tid & 3) * 4;       // 0,4,8,12

    float acc[4][4] = {};
    for (int k0 = 0; k0 < NC; k0 += 16) {
        float4 av = *(const float4*)&x[(m0 + lm) * NC + k0 + lk];
        float4 bv = *(const float4*)&W[(n0 + lm) * NC + k0 + lk];
        As[lk+0][lm] = av.x; As[lk+1][lm] = av.y; As[lk+2][lm] = av.z; As[lk+3][lm] = av.w;
        Bs[lk+0][lm] = bv.x; Bs[lk+1][lm] = bv.y; Bs[lk+2][lm] = bv.z; Bs[lk+3][lm] = bv.w;
        __syncthreads();
#pragma unroll
        for (int kk = 0; kk < 16; kk++) {
            float a[4], b[4];
#pragma unroll
            for (int i = 0; i < 4; i++) a[i] = As[kk][ty*4 + i];
#pragma unroll
            for (int j = 0; j < 4; j++) b[j] = Bs[kk][tx*4 + j];
#pragma unroll
            for (int i = 0; i < 4; i++)
#pragma unroll
                for (int j = 0; j < 4; j++) acc[i][j] += a[i] * b[j];
        }
        __syncthreads();
    }
#pragma unroll
    for (int i = 0; i < 4; i++) {
        int m = m0 + ty*4 + i;
        int b = m >> 11, t = m & 2047;
#pragma unroll
        for (int j = 0; j < 4; j++) {
            int n = n0 + tx*4 + j;
            int h = n >> 5, d = n & 31;
            outp[(((b*NH + h)*NT + t) << 5) + d] = acc[i][j] + bias[n];
        }
    }
}

// ---------------------------------------------------------------------------
// Pass 1: per-row softmax stats (m, l). Grid (NT/64, NH, NB), 256 threads.
// ---------------------------------------------------------------------------
__global__ __launch_bounds__(256) void attn_pass1() {
    int b = blockIdx.z, h = blockIdx.y, q0 = blockIdx.x * 64;
    __shared__ float Qs[64][33];
    __shared__ float Ks[64][33];
    int tid = threadIdx.x, tx = tid & 15, ty = tid >> 4;

    const float* qp = g_q + (size_t)(b*NH + h) * NT * ND;
    const float* kp = g_k + (size_t)(b*NH + h) * NT * ND;

    for (int i = tid; i < 64*32; i += 256) {
        int r = i >> 5, d = i & 31;
        Qs[r][d] = qp[(q0 + r)*ND + d];
    }
    float slope = exp2f(-(float)(h + 1) * (1.0f/16.0f));
    float mreg[4], lreg[4];
#pragma unroll
    for (int i = 0; i < 4; i++) { mreg[i] = -1e30f; lreg[i] = 0.0f; }

    for (int k0 = 0; k0 < NT; k0 += 64) {
        __syncthreads();
        for (int i = tid; i < 64*32; i += 256) {
            int r = i >> 5, d = i & 31;
            Ks[r][d] = kp[(k0 + r)*ND + d];
        }
        __syncthreads();
        float s[4][4] = {};
#pragma unroll
        for (int d = 0; d < 32; d++) {
            float a[4], bb[4];
#pragma unroll
            for (int i = 0; i < 4; i++) a[i] = Qs[ty*4 + i][d];
#pragma unroll
            for (int j = 0; j < 4; j++) bb[j] = Ks[tx*4 + j][d];
#pragma unroll
            for (int i = 0; i < 4; i++)
#pragma unroll
                for (int j = 0; j < 4; j++) s[i][j] += a[i] * bb[j];
        }
#pragma unroll
        for (int i = 0; i < 4; i++) {
            int qi = q0 + ty*4 + i;
            float rmax = -1e30f;
#pragma unroll
            for (int j = 0; j < 4; j++) {
                s[i][j] = s[i][j] * SCALE + slope * (float)(qi - (k0 + tx*4 + j));
                rmax = fmaxf(rmax, s[i][j]);
            }
#pragma unroll
            for (int off = 8; off; off >>= 1)
                rmax = fmaxf(rmax, __shfl_xor_sync(0xffffffffu, rmax, off, 16));
            float mnew = fmaxf(mreg[i], rmax);
            float ssum = 0.0f;
#pragma unroll
            for (int j = 0; j < 4; j++) ssum += __expf(s[i][j] - mnew);
#pragma unroll
            for (int off = 8; off; off >>= 1)
                ssum += __shfl_xor_sync(0xffffffffu, ssum, off, 16);
            lreg[i] = lreg[i] * __expf(mreg[i] - mnew) + ssum;
            mreg[i] = mnew;
        }
    }
    if (tx == 0) {
#pragma unroll
        for (int i = 0; i < 4; i++) {
            int idx = (b*NH + h)*NT + q0 + ty*4 + i;
            g_m[idx] = mreg[i];
            g_l[idx] = lreg[i];
        }
    }
}

// ---------------------------------------------------------------------------
// Pass 2: O = softmax(S) @ V using saved (m, l). Grid (NT/64, NH, NB).
// ---------------------------------------------------------------------------
__global__ __launch_bounds__(256) void attn_pass2() {
    int b = blockIdx.z, h = blockIdx.y, q0 = blockIdx.x * 64;
    __shared__ float Qs[64][33];
    __shared__ float Ks[64][33];
    __shared__ float Vs[64][34];
    __shared__ float Ps[64][65];
    __shared__ float smx[64], sli[64];
    int tid = threadIdx.x, tx = tid & 15, ty = tid >> 4;

    const float* qp = g_q + (size_t)(b*NH + h) * NT * ND;
    const float* kp = g_k + (size_t)(b*NH + h) * NT * ND;
    const float* vp = g_v + (size_t)(b*NH + h) * NT * ND;

    for (int i = tid; i < 64*32; i += 256) {
        int r = i >> 5, d = i & 31;
        Qs[r][d] = qp[(q0 + r)*ND + d];
    }
    if (tid < 64) {
        int idx = (b*NH + h)*NT + q0 + tid;
        smx[tid] = g_m[idx];
        sli[tid] = 1.0f / g_l[idx];
    }
    float slope = exp2f(-(float)(h + 1) * (1.0f/16.0f));
    float o[8] = {};
    int dcol = tid & 31, qb = (tid >> 5) * 8;

    for (int k0 = 0; k0 < NT; k0 += 64) {
        __syncthreads();
        for (int i = tid; i < 64*32; i += 256) {
            int r = i >> 5, d = i & 31;
            Ks[r][d] = kp[(k0 + r)*ND + d];
            Vs[r][d] = vp[(k0 + r)*ND + d];
        }
        __syncthreads();
        float s[4][4] = {};
#pragma unroll
        for (int d = 0; d < 32; d++) {
            float a[4], bb[4];
#pragma unroll
            for (int i = 0; i < 4; i++) a[i] = Qs[ty*4 + i][d];
#pragma unroll
            for (int j = 0; j < 4; j++) bb[j] = Ks[tx*4 + j][d];
#pragma unroll
            for (int i = 0; i < 4; i++)
#pragma unroll
                for (int j = 0; j < 4; j++) s[i][j] += a[i] * bb[j];
        }
#pragma unroll
        for (int i = 0; i < 4; i++) {
            int qi = q0 + ty*4 + i;
            float mi = smx[ty*4 + i];
            float il = sli[ty*4 + i];
#pragma unroll
            for (int j = 0; j < 4; j++) {
                float p = __expf(s[i][j] * SCALE + slope * (float)(qi - (k0 + tx*4 + j)) - mi) * il;
                Ps[ty*4 + i][tx*4 + j] = p;
            }
        }
        __syncthreads();
#pragma unroll 16
        for (int kk = 0; kk < 64; kk++) {
            float vv = Vs[kk][dcol];
#pragma unroll
            for (int i = 0; i < 8; i++) o[i] += Ps[qb + i][kk] * vv;
        }
    }
#pragma unroll
    for (int i = 0; i < 8; i++)
        g_o[((size_t)(b*NH + h)*NT + q0 + qb + i)*ND + dcol] = o[i];
}

// ---------------------------------------------------------------------------
// avg_probs: per (b, qtile, ktile) loop all heads, sum probs in registers,
// single deterministic store. Grid (NT/64 k, NT/64 q, NB).
// ---------------------------------------------------------------------------
__global__ __launch_bounds__(256) void attn_avg(float* __restrict__ avg) {
    int b = blockIdx.z, q0 = blockIdx.y * 64, k0 = blockIdx.x * 64;
    __shared__ float Qs[64][33];
    __shared__ float Ks[64][33];
    __shared__ float smx[64], sli[64];
    int tid = threadIdx.x, tx = tid & 15, ty = tid >> 4;
    float acc[4][4] = {};

    for (int h = 0; h < NH; h++) {
        const float* qp = g_q + ((size_t)(b*NH + h)*NT + q0) * ND;
        const float* kp = g_k + ((size_t)(b*NH + h)*NT + k0) * ND;
        __syncthreads();
        for (int i = tid; i < 64*32; i += 256) {
            int r = i >> 5, d = i & 31;
            Qs[r][d] = qp[r*ND + d];
            Ks[r][d] = kp[r*ND + d];
        }
        if (tid < 64) {
            int idx = (b*NH + h)*NT + q0 + tid;
            smx[tid] = g_m[idx];
            sli[tid] = 1.0f / g_l[idx];
        }
        __syncthreads();
        float slope = exp2f(-(float)(h + 1) * (1.0f/16.0f));
        float s[4][4] = {};
#pragma unroll
        for (int d = 0; d < 32; d++) {
            float a[4], bb[4];
#pragma unroll
            for (int i = 0; i < 4; i++) a[i] = Qs[ty*4 + i][d];
#pragma unroll
            for (int j = 0; j < 4; j++) bb[j] = Ks[tx*4 + j][d];
#pragma unroll
            for (int i = 0; i < 4; i++)
#pragma unroll
                for (int j = 0; j < 4; j++) s[i][j] += a[i] * bb[j];
        }
#pragma unroll
        for (int i = 0; i < 4; i++) {
            int qi = q0 + ty*4 + i;
            float mi = smx[ty*4 + i];
            float il = sli[ty*4 + i];
#pragma unroll
            for (int j = 0; j < 4; j++) {
                acc[i][j] += __expf(s[i][j] * SCALE + slope * (float)(qi - (k0 + tx*4 + j)) - mi) * il;
            }
        }
    }
#pragma unroll
    for (int i = 0; i < 4; i++)
#pragma unroll
        for (int j = 0; j < 4; j++)
            avg[((size_t)b*NT + q0 + ty*4 + i)*NT + k0 + tx*4 + j] = acc[i][j] * (1.0f/16.0f);
}

// ---------------------------------------------------------------------------
// Output projection: out[m][n] = sum_k A[m][k]*Wo[n][k] + bo[n], where
// A[m=(b,t)][k=(h,d)] is gathered from g_o (B,H,T,D). Grid (BT/64, NC/64).
// ---------------------------------------------------------------------------
__global__ __launch_bounds__(256) void gemm_out(const float* __restrict__ Wo,
                                               const float* __restrict__ bo,
                                               float* __restrict__ out) {
    __shared__ float As[16][65];
    __shared__ float Bs[16][65];
    int m0 = blockIdx.x * 64;
    int n0 = blockIdx.y * 64;
    int tid = threadIdx.x;
    int tx = tid & 15, ty = tid >> 4;
    int lm = tid >> 2;
    int lk = (tid & 3) * 4;

    float acc[4][4] = {};
    for (int k0 = 0; k0 < NC; k0 += 16) {
        int m = m0 + lm;
        int bb_ = m >> 11, t = m & 2047;
        int kidx = k0 + lk;
        int h = kidx >> 5, d = kidx & 31;
        float4 av = *(const float4*)&g_o[(((size_t)(bb_*NH + h)*NT + t) << 5) + d];
        float4 bv = *(const float4*)&Wo[(n0 + lm) * NC + k0 + lk];
        As[lk+0][lm] = av.x; As[lk+1][lm] = av.y; As[lk+2][lm] = av.z; As[lk+3][lm] = av.w;
        Bs[lk+0][lm] = bv.x; Bs[lk+1][lm] = bv.y; Bs[lk+2][lm] = bv.z; Bs[lk+3][lm] = bv.w;
        __syncthreads();
#pragma unroll
        for (int kk = 0; kk < 16; kk++) {
            float a[4], b[4];
#pragma unroll
            for (int i = 0; i < 4; i++) a[i] = As[kk][ty*4 + i];
#pragma unroll
            for (int j = 0; j < 4; j++) b[j] = Bs[kk][tx*4 + j];
#pragma unroll
            for (int i = 0; i < 4; i++)
#pragma unroll
                for (int j = 0; j < 4; j++) acc[i][j] += a[i] * b[j];
        }
        __syncthreads();
    }
#pragma unroll
    for (int i = 0; i < 4; i++) {
        int m = m0 + ty*4 + i;
#pragma unroll
        for (int j = 0; j < 4; j++) {
            int n = n0 + tx*4 + j;
            out[(size_t)m * NC + n] = acc[i][j] + bo[n];
        }
    }
}

// ---------------------------------------------------------------------------
extern "C" void kernel_launch(void* const* d_in, const int* in_sizes, int n_in,
                              void* d_out, int out_size) {
    const float* x  = (const float*)d_in[0];
    const float* Wq = (const float*)d_in[1];
    const float* bq = (const float*)d_in[2];
    const float* Wk = (const float*)d_in[3];
    const float* bk = (const float*)d_in[4];
    const float* Wv = (const float*)d_in[5];
    const float* bv = (const float*)d_in[6];
    const float* Wo = (const float*)d_in[7];
    const float* bo = (const float*)d_in[8];

    float* out = (float*)d_out;                 // (B,T,C)
    float* avg = out + (size_t)NB*NT*NC;        // (B,T,T)

    dim3 gg(BT/64, NC/64);
    gemm_qkv<<<gg, 256>>>(x, Wq, bq, 0);
    gemm_qkv<<<gg, 256>>>(x, Wk, bk, 1);
    gemm_qkv<<<gg, 256>>>(x, Wv, bv, 2);

    dim3 ga(NT/64, NH, NB);
    attn_pass1<<<ga, 256>>>();
    attn_pass2<<<ga, 256>>>();

    dim3 gv(NT/64, NT/64, NB);
    attn_avg<<<gv, 256>>>(avg);

    gemm_out<<<gg, 256>>>(Wo, bo, out);
}

// round 3
// speedup vs baseline: 3.6233x; 3.6233x over previous
#include <cuda_runtime.h>

#define NB 2
#define NT 2048
#define NC 512
#define NH 16
#define ND 32
#define BT (NB*NT)          // 4096
#define SCALE 0.17677669529663687f   // 1/sqrt(32)

// Scratch (device globals: allocation-free)
__device__ float g_q[NB*NH*NT*ND];
__device__ float g_k[NB*NH*NT*ND];
__device__ float g_v[NB*NH*NT*ND];
__device__ float g_o[NB*NH*NT*ND];
__device__ float g_m[NB*NH*NT];
__device__ float g_l[NB*NH*NT];

__device__ __forceinline__ unsigned f2tf(float f) {
    unsigned u; asm("cvt.rna.tf32.f32 %0, %1;" : "=r"(u) : "f"(f)); return u;
}

// D += A*B, m16n8k8 tf32. A row-major frags a0..a3, B col-major frags b0,b1.
__device__ __forceinline__ void mma8(float d[4], const unsigned a[4], const unsigned b[2]) {
    asm("mma.sync.aligned.m16n8k8.row.col.f32.tf32.tf32.f32 "
        "{%0,%1,%2,%3},{%4,%5,%6,%7},{%8,%9},{%0,%1,%2,%3};"
        : "+f"(d[0]), "+f"(d[1]), "+f"(d[2]), "+f"(d[3])
        : "r"(a[0]), "r"(a[1]), "r"(a[2]), "r"(a[3]), "r"(b[0]), "r"(b[1]));
}

// ---------------------------------------------------------------------------
// QKV projection, tf32 mma. y[m][n] = sum_k x[m][k]*W[n][k] + bias[n],
// scattered to (B,H,T,D). Grid (BT/128, NC/64, 3), 256 threads.
// ---------------------------------------------------------------------------
__global__ __launch_bounds__(256) void gemm_qkv(const float* __restrict__ x,
    const float* __restrict__ Wq, const float* __restrict__ bq,
    const float* __restrict__ Wk, const float* __restrict__ bk,
    const float* __restrict__ Wv, const float* __restrict__ bv) {
    int sel = blockIdx.z;
    const float* W    = sel == 0 ? Wq : (sel == 1 ? Wk : Wv);
    const float* bias = sel == 0 ? bq : (sel == 1 ? bk : bv);
    float* outp       = sel == 0 ? g_q : (sel == 1 ? g_k : g_v);

    __shared__ unsigned As[128][20];
    __shared__ unsigned Bs[64][20];
    int m0 = blockIdx.x * 128, n0 = blockIdx.y * 64;
    int tid = threadIdx.x, wid = tid >> 5, lane = tid & 31, g = lane >> 2, t = lane & 3;
    int wm = (wid & 3) * 32, wn = (wid >> 2) * 32;

    float acc[2][4][4] = {};
    for (int k0 = 0; k0 < NC; k0 += 16) {
#pragma unroll
        for (int i = 0; i < 2; i++) {
            int idx = tid + i * 256; int r = idx >> 2, c = (idx & 3) * 4;
            float4 v = *(const float4*)&x[(size_t)(m0 + r) * NC + k0 + c];
            As[r][c] = f2tf(v.x); As[r][c+1] = f2tf(v.y); As[r][c+2] = f2tf(v.z); As[r][c+3] = f2tf(v.w);
        }
        {
            int r = tid >> 2, c = (tid & 3) * 4;
            float4 v = *(const float4*)&W[(size_t)(n0 + r) * NC + k0 + c];
            Bs[r][c] = f2tf(v.x); Bs[r][c+1] = f2tf(v.y); Bs[r][c+2] = f2tf(v.z); Bs[r][c+3] = f2tf(v.w);
        }
        __syncthreads();
#pragma unroll
        for (int kk = 0; kk < 16; kk += 8) {
            unsigned a[2][4], b[4][2];
#pragma unroll
            for (int mi = 0; mi < 2; mi++) {
                int rb = wm + mi * 16;
                a[mi][0] = As[rb + g][kk + t];     a[mi][1] = As[rb + g + 8][kk + t];
                a[mi][2] = As[rb + g][kk + t + 4]; a[mi][3] = As[rb + g + 8][kk + t + 4];
            }
#pragma unroll
            for (int ni = 0; ni < 4; ni++) {
                b[ni][0] = Bs[wn + ni * 8 + g][kk + t];
                b[ni][1] = Bs[wn + ni * 8 + g][kk + t + 4];
            }
#pragma unroll
            for (int mi = 0; mi < 2; mi++)
#pragma unroll
                for (int ni = 0; ni < 4; ni++) mma8(acc[mi][ni], a[mi], b[ni]);
        }
        __syncthreads();
    }
#pragma unroll
    for (int mi = 0; mi < 2; mi++) {
        int r0 = m0 + wm + mi * 16 + g;
        int r1 = r0 + 8;
        int b0i = r0 >> 11, t0 = r0 & 2047;
        int b1i = r1 >> 11, t1 = r1 & 2047;
#pragma unroll
        for (int ni = 0; ni < 4; ni++) {
            int n = n0 + wn + ni * 8 + 2 * t;
            int h = n >> 5, d = n & 31;
            float bb0 = bias[n], bb1 = bias[n + 1];
            *(float2*)&outp[(((size_t)(b0i * NH + h) * NT + t0)) * ND + d] =
                make_float2(acc[mi][ni][0] + bb0, acc[mi][ni][1] + bb1);
            *(float2*)&outp[(((size_t)(b1i * NH + h) * NT + t1)) * ND + d] =
                make_float2(acc[mi][ni][2] + bb0, acc[mi][ni][3] + bb1);
        }
    }
}

// ---------------------------------------------------------------------------
// Fused flash attention (pass1+pass2): online softmax, O = P@V, stores m,l.
// Grid (NT/64, NH, NB), 128 threads (4 warps, 16 q-rows each).
// ---------------------------------------------------------------------------
__global__ __launch_bounds__(128) void flash_attn() {
    int q0 = blockIdx.x * 64, h = blockIdx.y, b = blockIdx.z;
    int bh = b * NH + h;
    __shared__ unsigned Qs[64][36];
    __shared__ unsigned Ks[64][36];
    __shared__ unsigned Vs[64][40];
    __shared__ unsigned Ps[64][68];
    int tid = threadIdx.x, wid = tid >> 5, lane = tid & 31, g = lane >> 2, t = lane & 3;
    int wm = wid * 16;
    const float* qp = g_q + (size_t)bh * NT * ND;
    const float* kp = g_k + (size_t)bh * NT * ND;
    const float* vp = g_v + (size_t)bh * NT * ND;

#pragma unroll
    for (int i = 0; i < 4; i++) {
        int idx = tid + i * 128; int r = idx >> 3, c = (idx & 7) * 4;
        float4 v = *(const float4*)&qp[(size_t)(q0 + r) * ND + c];
        Qs[r][c] = f2tf(v.x); Qs[r][c+1] = f2tf(v.y); Qs[r][c+2] = f2tf(v.z); Qs[r][c+3] = f2tf(v.w);
    }
    float slope = exp2f(-(float)(h + 1) * (1.0f / 16.0f));
    float mr0 = -1e30f, mr1 = -1e30f, l0 = 0.f, l1 = 0.f;
    float oacc[4][4] = {};
    int qi0 = q0 + wm + g, qi1 = qi0 + 8;

    for (int kt = 0; kt < NT; kt += 64) {
        __syncthreads();
#pragma unroll
        for (int i = 0; i < 4; i++) {
            int idx = tid + i * 128; int r = idx >> 3, c = (idx & 7) * 4;
            float4 kv4 = *(const float4*)&kp[(size_t)(kt + r) * ND + c];
            float4 vv4 = *(const float4*)&vp[(size_t)(kt + r) * ND + c];
            Ks[r][c] = f2tf(kv4.x); Ks[r][c+1] = f2tf(kv4.y); Ks[r][c+2] = f2tf(kv4.z); Ks[r][c+3] = f2tf(kv4.w);
            Vs[r][c] = f2tf(vv4.x); Vs[r][c+1] = f2tf(vv4.y); Vs[r][c+2] = f2tf(vv4.z); Vs[r][c+3] = f2tf(vv4.w);
        }
        __syncthreads();
        float sacc[8][4] = {};
#pragma unroll
        for (int kk = 0; kk < 32; kk += 8) {
            unsigned a[4] = { Qs[wm + g][kk + t], Qs[wm + g + 8][kk + t],
                              Qs[wm + g][kk + t + 4], Qs[wm + g + 8][kk + t + 4] };
#pragma unroll
            for (int ni = 0; ni < 8; ni++) {
                unsigned bf[2] = { Ks[ni * 8 + g][kk + t], Ks[ni * 8 + g][kk + t + 4] };
                mma8(sacc[ni], a, bf);
            }
        }
        float rmax0 = -1e30f, rmax1 = -1e30f;
#pragma unroll
        for (int ni = 0; ni < 8; ni++) {
            float kj = (float)(kt + ni * 8 + 2 * t);
            sacc[ni][0] = sacc[ni][0] * SCALE + slope * ((float)qi0 - kj);
            sacc[ni][1] = sacc[ni][1] * SCALE + slope * ((float)qi0 - kj - 1.f);
            sacc[ni][2] = sacc[ni][2] * SCALE + slope * ((float)qi1 - kj);
            sacc[ni][3] = sacc[ni][3] * SCALE + slope * ((float)qi1 - kj - 1.f);
            rmax0 = fmaxf(rmax0, fmaxf(sacc[ni][0], sacc[ni][1]));
            rmax1 = fmaxf(rmax1, fmaxf(sacc[ni][2], sacc[ni][3]));
        }
        rmax0 = fmaxf(rmax0, __shfl_xor_sync(~0u, rmax0, 1));
        rmax0 = fmaxf(rmax0, __shfl_xor_sync(~0u, rmax0, 2));
        rmax1 = fmaxf(rmax1, __shfl_xor_sync(~0u, rmax1, 1));
        rmax1 = fmaxf(rmax1, __shfl_xor_sync(~0u, rmax1, 2));
        float mn0 = fmaxf(mr0, rmax0), mn1 = fmaxf(mr1, rmax1);
        float al0 = __expf(mr0 - mn0), al1 = __expf(mr1 - mn1);
        float rs0 = 0.f, rs1 = 0.f;
#pragma unroll
        for (int ni = 0; ni < 8; ni++) {
            float p0 = __expf(sacc[ni][0] - mn0);
            float p1 = __expf(sacc[ni][1] - mn0);
            float p2 = __expf(sacc[ni][2] - mn1);
            float p3 = __expf(sacc[ni][3] - mn1);
            rs0 += p0 + p1; rs1 += p2 + p3;
            int col = ni * 8 + 2 * t;
            Ps[wm + g][col] = f2tf(p0);     Ps[wm + g][col + 1] = f2tf(p1);
            Ps[wm + g + 8][col] = f2tf(p2); Ps[wm + g + 8][col + 1] = f2tf(p3);
        }
        rs0 += __shfl_xor_sync(~0u, rs0, 1); rs0 += __shfl_xor_sync(~0u, rs0, 2);
        rs1 += __shfl_xor_sync(~0u, rs1, 1); rs1 += __shfl_xor_sync(~0u, rs1, 2);
        l0 = l0 * al0 + rs0; l1 = l1 * al1 + rs1; mr0 = mn0; mr1 = mn1;
#pragma unroll
        for (int ni = 0; ni < 4; ni++) {
            oacc[ni][0] *= al0; oacc[ni][1] *= al0; oacc[ni][2] *= al1; oacc[ni][3] *= al1;
        }
        __syncwarp();
#pragma unroll
        for (int kk = 0; kk < 64; kk += 8) {
            unsigned a[4] = { Ps[wm + g][kk + t], Ps[wm + g + 8][kk + t],
                              Ps[wm + g][kk + t + 4], Ps[wm + g + 8][kk + t + 4] };
#pragma unroll
            for (int ni = 0; ni < 4; ni++) {
                unsigned bf[2] = { Vs[kk + t][ni * 8 + g], Vs[kk + t + 4][ni * 8 + g] };
                mma8(oacc[ni], a, bf);
            }
        }
    }
    float il0 = 1.f / l0, il1 = 1.f / l1;
#pragma unroll
    for (int ni = 0; ni < 4; ni++) {
        int col = ni * 8 + 2 * t;
        *(float2*)&g_o[((size_t)bh * NT + qi0) * ND + col] =
            make_float2(oacc[ni][0] * il0, oacc[ni][1] * il0);
        *(float2*)&g_o[((size_t)bh * NT + qi1) * ND + col] =
            make_float2(oacc[ni][2] * il1, oacc[ni][3] * il1);
    }
    if (t == 0) {
        g_m[(size_t)bh * NT + qi0] = mr0; g_l[(size_t)bh * NT + qi0] = l0;
        g_m[(size_t)bh * NT + qi1] = mr1; g_l[(size_t)bh * NT + qi1] = l1;
    }
}

// ---------------------------------------------------------------------------
// avg_probs: per (b, 128-q-tile, 64-k-tile) loop all 16 heads with saved m,l.
// Grid (NT/64, NT/128, NB), 256 threads (8 warps, 16 q-rows each).
// ---------------------------------------------------------------------------
__global__ __launch_bounds__(256) void attn_avg(float* __restrict__ avg) {
    int k0 = blockIdx.x * 64, q0 = blockIdx.y * 128, b = blockIdx.z;
    __shared__ unsigned Qs[128][36];
    __shared__ unsigned Ks[64][36];
    __shared__ float smx[128], sil[128];
    int tid = threadIdx.x, wid = tid >> 5, lane = tid & 31, g = lane >> 2, t = lane & 3;
    int wm = wid * 16;
    int qi0 = q0 + wm + g, qi1 = qi0 + 8;
    float acc[8][4] = {};

    for (int h = 0; h < NH; h++) {
        int bh = b * NH + h;
        const float* qp = g_q + ((size_t)bh * NT + q0) * ND;
        const float* kp = g_k + ((size_t)bh * NT + k0) * ND;
        __syncthreads();
#pragma unroll
        for (int i = 0; i < 4; i++) {
            int idx = tid + i * 256; int r = idx >> 3, c = (idx & 7) * 4;
            float4 v = *(const float4*)&qp[(size_t)r * ND + c];
            Qs[r][c] = f2tf(v.x); Qs[r][c+1] = f2tf(v.y); Qs[r][c+2] = f2tf(v.z); Qs[r][c+3] = f2tf(v.w);
        }
#pragma unroll
        for (int i = 0; i < 2; i++) {
            int idx = tid + i * 256; int r = idx >> 3, c = (idx & 7) * 4;
            float4 v = *(const float4*)&kp[(size_t)r * ND + c];
            Ks[r][c] = f2tf(v.x); Ks[r][c+1] = f2tf(v.y); Ks[r][c+2] = f2tf(v.z); Ks[r][c+3] = f2tf(v.w);
        }
        if (tid < 128) {
            smx[tid] = g_m[(size_t)bh * NT + q0 + tid];
            sil[tid] = 1.f / g_l[(size_t)bh * NT + q0 + tid];
        }
        __syncthreads();
        float slope = exp2f(-(float)(h + 1) * (1.0f / 16.0f));
        float sacc[8][4] = {};
#pragma unroll
        for (int kk = 0; kk < 32; kk += 8) {
            unsigned a[4] = { Qs[wm + g][kk + t], Qs[wm + g + 8][kk + t],
                              Qs[wm + g][kk + t + 4], Qs[wm + g + 8][kk + t + 4] };
#pragma unroll
            for (int ni = 0; ni < 8; ni++) {
                unsigned bf[2] = { Ks[ni * 8 + g][kk + t], Ks[ni * 8 + g][kk + t + 4] };
                mma8(sacc[ni], a, bf);
            }
        }
        float m0v = smx[wm + g], i0v = sil[wm + g];
        float m1v = smx[wm + g + 8], i1v = sil[wm + g + 8];
#pragma unroll
        for (int ni = 0; ni < 8; ni++) {
            float kj = (float)(k0 + ni * 8 + 2 * t);
            acc[ni][0] += __expf(sacc[ni][0] * SCALE + slope * ((float)qi0 - kj) - m0v) * i0v;
            acc[ni][1] += __expf(sacc[ni][1] * SCALE + slope * ((float)qi0 - kj - 1.f) - m0v) * i0v;
            acc[ni][2] += __expf(sacc[ni][2] * SCALE + slope * ((float)qi1 - kj) - m1v) * i1v;
            acc[ni][3] += __expf(sacc[ni][3] * SCALE + slope * ((float)qi1 - kj - 1.f) - m1v) * i1v;
        }
    }
#pragma unroll
    for (int ni = 0; ni < 8; ni++) {
        int col = k0 + ni * 8 + 2 * t;
        *(float2*)&avg[((size_t)b * NT + qi0) * NT + col] =
            make_float2(acc[ni][0] * 0.0625f, acc[ni][1] * 0.0625f);
        *(float2*)&avg[((size_t)b * NT + qi1) * NT + col] =
            make_float2(acc[ni][2] * 0.0625f, acc[ni][3] * 0.0625f);
    }
}

// ---------------------------------------------------------------------------
// Output projection, tf32 mma, gathers A from g_o (B,H,T,D)->(B,T,C).
// Grid (BT/128, NC/64), 256 threads.
// ---------------------------------------------------------------------------
__global__ __launch_bounds__(256) void gemm_out(const float* __restrict__ Wo,
                                               const float* __restrict__ bo,
                                               float* __restrict__ out) {
    __shared__ unsigned As[128][20];
    __shared__ unsigned Bs[64][20];
    int m0 = blockIdx.x * 128, n0 = blockIdx.y * 64;
    int tid = threadIdx.x, wid = tid >> 5, lane = tid & 31, g = lane >> 2, t = lane & 3;
    int wm = (wid & 3) * 32, wn = (wid >> 2) * 32;

    float acc[2][4][4] = {};
    for (int k0 = 0; k0 < NC; k0 += 16) {
#pragma unroll
        for (int i = 0; i < 2; i++) {
            int idx = tid + i * 256; int r = idx >> 2, c = (idx & 3) * 4;
            int m = m0 + r; int bi = m >> 11, tt = m & 2047;
            int k = k0 + c; int h = k >> 5, d = k & 31;
            float4 v = *(const float4*)&g_o[((size_t)(bi * NH + h) * NT + tt) * ND + d];
            As[r][c] = f2tf(v.x); As[r][c+1] = f2tf(v.y); As[r][c+2] = f2tf(v.z); As[r][c+3] = f2tf(v.w);
        }
        {
            int r = tid >> 2, c = (tid & 3) * 4;
            float4 v = *(const float4*)&Wo[(size_t)(n0 + r) * NC + k0 + c];
            Bs[r][c] = f2tf(v.x); Bs[r][c+1] = f2tf(v.y); Bs[r][c+2] = f2tf(v.z); Bs[r][c+3] = f2tf(v.w);
        }
        __syncthreads();
#pragma unroll
        for (int kk = 0; kk < 16; kk += 8) {
            unsigned a[2][4], b[4][2];
#pragma unroll
            for (int mi = 0; mi < 2; mi++) {
                int rb = wm + mi * 16;
                a[mi][0] = As[rb + g][kk + t];     a[mi][1] = As[rb + g + 8][kk + t];
                a[mi][2] = As[rb + g][kk + t + 4]; a[mi][3] = As[rb + g + 8][kk + t + 4];
            }
#pragma unroll
            for (int ni = 0; ni < 4; ni++) {
                b[ni][0] = Bs[wn + ni * 8 + g][kk + t];
                b[ni][1] = Bs[wn + ni * 8 + g][kk + t + 4];
            }
#pragma unroll
            for (int mi = 0; mi < 2; mi++)
#pragma unroll
                for (int ni = 0; ni < 4; ni++) mma8(acc[mi][ni], a[mi], b[ni]);
        }
        __syncthreads();
    }
#pragma unroll
    for (int mi = 0; mi < 2; mi++) {
        int r0 = m0 + wm + mi * 16 + g;
        int r1 = r0 + 8;
#pragma unroll
        for (int ni = 0; ni < 4; ni++) {
            int n = n0 + wn + ni * 8 + 2 * t;
            float bb0 = bo[n], bb1 = bo[n + 1];
            *(float2*)&out[(size_t)r0 * NC + n] = make_float2(acc[mi][ni][0] + bb0, acc[mi][ni][1] + bb1);
            *(float2*)&out[(size_t)r1 * NC + n] = make_float2(acc[mi][ni][2] + bb0, acc[mi][ni][3] + bb1);
        }
    }
}

// ---------------------------------------------------------------------------
extern "C" void kernel_launch(void* const* d_in, const int* in_sizes, int n_in,
                              void* d_out, int out_size) {
    const float* x  = (const float*)d_in[0];
    const float* Wq = (const float*)d_in[1];
    const float* bq = (const float*)d_in[2];
    const float* Wk = (const float*)d_in[3];
    const float* bk = (const float*)d_in[4];
    const float* Wv = (const float*)d_in[5];
    const float* bv = (const float*)d_in[6];
    const float* Wo = (const float*)d_in[7];
    const float* bo = (const float*)d_in[8];

    float* out = (float*)d_out;                 // (B,T,C)
    float* avg = out + (size_t)NB*NT*NC;        // (B,T,T)

    dim3 g1(BT/128, NC/64, 3);
    gemm_qkv<<<g1, 256>>>(x, Wq, bq, Wk, bk, Wv, bv);

    dim3 g2(NT/64, NH, NB);
    flash_attn<<<g2, 128>>>();

    dim3 g3(NT/64, NT/128, NB);
    attn_avg<<<g3, 256>>>(avg);

    dim3 g4(BT/128, NC/64);
    gemm_out<<<g4, 256>>>(Wo, bo, out);
}

// round 4
// speedup vs baseline: 3.6739x; 1.0140x over previous
#include <cuda_runtime.h>

#define NB 2
#define NT 2048
#define NC 512
#define NH 16
#define ND 32
#define BT (NB*NT)          // 4096
#define SCALE 0.17677669529663687f   // 1/sqrt(32)

// Scratch (device globals: allocation-free). q/k/v/o hold tf32-rounded values.
__device__ float g_q[NB*NH*NT*ND];
__device__ float g_k[NB*NH*NT*ND];
__device__ float g_v[NB*NH*NT*ND];
__device__ float g_o[NB*NH*NT*ND];
__device__ float g_m[NB*NH*NT];
__device__ float g_l[NB*NH*NT];

__device__ __forceinline__ unsigned f2tf(float f) {
    unsigned u; asm("cvt.rna.tf32.f32 %0, %1;" : "=r"(u) : "f"(f)); return u;
}

// D += A*B, m16n8k8 tf32.
__device__ __forceinline__ void mma8(float d[4], const unsigned a[4], const unsigned b[2]) {
    asm("mma.sync.aligned.m16n8k8.row.col.f32.tf32.tf32.f32 "
        "{%0,%1,%2,%3},{%4,%5,%6,%7},{%8,%9},{%0,%1,%2,%3};"
        : "+f"(d[0]), "+f"(d[1]), "+f"(d[2]), "+f"(d[3])
        : "r"(a[0]), "r"(a[1]), "r"(a[2]), "r"(a[3]), "r"(b[0]), "r"(b[1]));
}

__device__ __forceinline__ void cpa16(void* s, const void* g) {
    unsigned sa = (unsigned)__cvta_generic_to_shared(s);
    asm volatile("cp.async.cg.shared.global [%0], [%1], 16;" :: "r"(sa), "l"(g));
}
__device__ __forceinline__ void cpcommit() { asm volatile("cp.async.commit_group;"); }
template<int N> __device__ __forceinline__ void cpwait() {
    asm volatile("cp.async.wait_group %0;" :: "n"(N));
}

// ---------------------------------------------------------------------------
// QKV projection, tf32 mma, cp.async double-buffered over K-steps.
// Stores tf32-ROUNDED values scattered to (B,H,T,D).
// Grid (BT/128, NC/64, 3), 256 threads.
// ---------------------------------------------------------------------------
__global__ __launch_bounds__(256,2) void gemm_qkv(const float* __restrict__ x,
    const float* __restrict__ Wq, const float* __restrict__ bq,
    const float* __restrict__ Wk, const float* __restrict__ bk,
    const float* __restrict__ Wv, const float* __restrict__ bv) {
    __shared__ float As[2][128][20];
    __shared__ float Bs[2][64][20];
    int sel = blockIdx.z;
    const float* W    = sel == 0 ? Wq : (sel == 1 ? Wk : Wv);
    const float* bias = sel == 0 ? bq : (sel == 1 ? bk : bv);
    float* outp       = sel == 0 ? g_q : (sel == 1 ? g_k : g_v);

    int m0 = blockIdx.x * 128, n0 = blockIdx.y * 64;
    int tid = threadIdx.x, wid = tid >> 5, lane = tid & 31, g = lane >> 2, t = lane & 3;
    int wm = (wid & 3) * 32, wn = (wid >> 2) * 32;

    // prologue: k-step 0 into buffer 0
    {
#pragma unroll
        for (int i = 0; i < 2; i++) {
            int idx = tid + i * 256; int r = idx >> 2, c = (idx & 3) * 4;
            cpa16(&As[0][r][c], &x[(size_t)(m0 + r) * NC + c]);
        }
        int r = tid >> 2, c = (tid & 3) * 4;
        cpa16(&Bs[0][r][c], &W[(size_t)(n0 + r) * NC + c]);
        cpcommit();
    }

    float acc[2][4][4] = {};
    int cb = 0;
    for (int k0 = 0; k0 < NC; k0 += 16, cb ^= 1) {
        __syncthreads();
        if (k0 + 16 < NC) {
            int kn = k0 + 16;
#pragma unroll
            for (int i = 0; i < 2; i++) {
                int idx = tid + i * 256; int r = idx >> 2, c = (idx & 3) * 4;
                cpa16(&As[cb^1][r][c], &x[(size_t)(m0 + r) * NC + kn + c]);
            }
            int r = tid >> 2, c = (tid & 3) * 4;
            cpa16(&Bs[cb^1][r][c], &W[(size_t)(n0 + r) * NC + kn + c]);
            cpcommit(); cpwait<1>();
        } else cpwait<0>();
        __syncthreads();
#pragma unroll
        for (int kk = 0; kk < 16; kk += 8) {
            unsigned a[2][4], b[4][2];
#pragma unroll
            for (int mi = 0; mi < 2; mi++) {
                int rb = wm + mi * 16;
                a[mi][0] = f2tf(As[cb][rb + g][kk + t]);     a[mi][1] = f2tf(As[cb][rb + g + 8][kk + t]);
                a[mi][2] = f2tf(As[cb][rb + g][kk + t + 4]); a[mi][3] = f2tf(As[cb][rb + g + 8][kk + t + 4]);
            }
#pragma unroll
            for (int ni = 0; ni < 4; ni++) {
                b[ni][0] = f2tf(Bs[cb][wn + ni * 8 + g][kk + t]);
                b[ni][1] = f2tf(Bs[cb][wn + ni * 8 + g][kk + t + 4]);
            }
#pragma unroll
            for (int mi = 0; mi < 2; mi++)
#pragma unroll
                for (int ni = 0; ni < 4; ni++) mma8(acc[mi][ni], a[mi], b[ni]);
        }
    }
#pragma unroll
    for (int mi = 0; mi < 2; mi++) {
        int r0 = m0 + wm + mi * 16 + g;
        int r1 = r0 + 8;
        int b0i = r0 >> 11, t0 = r0 & 2047;
        int b1i = r1 >> 11, t1 = r1 & 2047;
#pragma unroll
        for (int ni = 0; ni < 4; ni++) {
            int n = n0 + wn + ni * 8 + 2 * t;
            int h = n >> 5, d = n & 31;
            float bb0 = bias[n], bb1 = bias[n + 1];
            *(float2*)&outp[((size_t)(b0i * NH + h) * NT + t0) * ND + d] =
                make_float2(__uint_as_float(f2tf(acc[mi][ni][0] + bb0)),
                            __uint_as_float(f2tf(acc[mi][ni][1] + bb1)));
            *(float2*)&outp[((size_t)(b1i * NH + h) * NT + t1) * ND + d] =
                make_float2(__uint_as_float(f2tf(acc[mi][ni][2] + bb0)),
                            __uint_as_float(f2tf(acc[mi][ni][3] + bb1)));
        }
    }
}

// ---------------------------------------------------------------------------
// Fused flash attention: 128-q-tile, 8 warps, cp.async double-buffered K/V.
// Inputs already tf32-rounded -> fragments used directly (no cvt).
// Grid (NT/128, NH, NB), 256 threads, dynamic smem.
// ---------------------------------------------------------------------------
struct FlashSmem {
    unsigned Qs[128][36];
    unsigned Ks[2][64][36];
    unsigned Vs[2][64][40];
    unsigned Ps[128][68];
};

__global__ __launch_bounds__(256,2) void flash_attn() {
    extern __shared__ char smraw[];
    FlashSmem& sm = *reinterpret_cast<FlashSmem*>(smraw);
    int q0 = blockIdx.x * 128, h = blockIdx.y, b = blockIdx.z;
    int bh = b * NH + h;
    int tid = threadIdx.x, wid = tid >> 5, lane = tid & 31, g = lane >> 2, t = lane & 3;
    int wm = wid * 16;
    const float* qp = g_q + (size_t)bh * NT * ND;
    const float* kp = g_k + (size_t)bh * NT * ND;
    const float* vp = g_v + (size_t)bh * NT * ND;

    // Q tile (values are tf32-clean floats; store raw bits)
#pragma unroll
    for (int i = 0; i < 4; i++) {
        int idx = tid + i * 256; int r = idx >> 3, c = (idx & 7) * 4;
        float4 v = *(const float4*)&qp[(size_t)(q0 + r) * ND + c];
        sm.Qs[r][c]   = __float_as_uint(v.x); sm.Qs[r][c+1] = __float_as_uint(v.y);
        sm.Qs[r][c+2] = __float_as_uint(v.z); sm.Qs[r][c+3] = __float_as_uint(v.w);
    }
    // prologue: K0,V0
#pragma unroll
    for (int i = 0; i < 2; i++) {
        int idx = tid + i * 256; int r = idx >> 3, c = (idx & 7) * 4;
        cpa16(&sm.Ks[0][r][c], &kp[(size_t)r * ND + c]);
        cpa16(&sm.Vs[0][r][c], &vp[(size_t)r * ND + c]);
    }
    cpcommit();

    float slope = exp2f(-(float)(h + 1) * (1.0f / 16.0f));
    float mr0 = -1e30f, mr1 = -1e30f, l0 = 0.f, l1 = 0.f;
    float oacc[4][4] = {};
    int qi0 = q0 + wm + g, qi1 = qi0 + 8;
    int cb = 0;

    for (int kt = 0; kt < NT; kt += 64, cb ^= 1) {
        __syncthreads();
        if (kt + 64 < NT) {
            const float* kp2 = kp + (size_t)(kt + 64) * ND;
            const float* vp2 = vp + (size_t)(kt + 64) * ND;
#pragma unroll
            for (int i = 0; i < 2; i++) {
                int idx = tid + i * 256; int r = idx >> 3, c = (idx & 7) * 4;
                cpa16(&sm.Ks[cb^1][r][c], &kp2[(size_t)r * ND + c]);
                cpa16(&sm.Vs[cb^1][r][c], &vp2[(size_t)r * ND + c]);
            }
            cpcommit(); cpwait<1>();
        } else cpwait<0>();
        __syncthreads();

        float sacc[8][4] = {};
#pragma unroll
        for (int kk = 0; kk < 32; kk += 8) {
            unsigned a[4] = { sm.Qs[wm + g][kk + t], sm.Qs[wm + g + 8][kk + t],
                              sm.Qs[wm + g][kk + t + 4], sm.Qs[wm + g + 8][kk + t + 4] };
#pragma unroll
            for (int ni = 0; ni < 8; ni++) {
                unsigned bf[2] = { sm.Ks[cb][ni * 8 + g][kk + t],
                                   sm.Ks[cb][ni * 8 + g][kk + t + 4] };
                mma8(sacc[ni], a, bf);
            }
        }
        float rmax0 = -1e30f, rmax1 = -1e30f;
#pragma unroll
        for (int ni = 0; ni < 8; ni++) {
            float kj = (float)(kt + ni * 8 + 2 * t);
            sacc[ni][0] = sacc[ni][0] * SCALE + slope * ((float)qi0 - kj);
            sacc[ni][1] = sacc[ni][1] * SCALE + slope * ((float)qi0 - kj - 1.f);
            sacc[ni][2] = sacc[ni][2] * SCALE + slope * ((float)qi1 - kj);
            sacc[ni][3] = sacc[ni][3] * SCALE + slope * ((float)qi1 - kj - 1.f);
            rmax0 = fmaxf(rmax0, fmaxf(sacc[ni][0], sacc[ni][1]));
            rmax1 = fmaxf(rmax1, fmaxf(sacc[ni][2], sacc[ni][3]));
        }
        rmax0 = fmaxf(rmax0, __shfl_xor_sync(~0u, rmax0, 1));
        rmax0 = fmaxf(rmax0, __shfl_xor_sync(~0u, rmax0, 2));
        rmax1 = fmaxf(rmax1, __shfl_xor_sync(~0u, rmax1, 1));
        rmax1 = fmaxf(rmax1, __shfl_xor_sync(~0u, rmax1, 2));
        float mn0 = fmaxf(mr0, rmax0), mn1 = fmaxf(mr1, rmax1);
        float al0 = __expf(mr0 - mn0), al1 = __expf(mr1 - mn1);
        float rs0 = 0.f, rs1 = 0.f;
#pragma unroll
        for (int ni = 0; ni < 8; ni++) {
            float p0 = __expf(sacc[ni][0] - mn0);
            float p1 = __expf(sacc[ni][1] - mn0);
            float p2 = __expf(sacc[ni][2] - mn1);
            float p3 = __expf(sacc[ni][3] - mn1);
            rs0 += p0 + p1; rs1 += p2 + p3;
            int col = ni * 8 + 2 * t;
            sm.Ps[wm + g][col] = f2tf(p0);     sm.Ps[wm + g][col + 1] = f2tf(p1);
            sm.Ps[wm + g + 8][col] = f2tf(p2); sm.Ps[wm + g + 8][col + 1] = f2tf(p3);
        }
        rs0 += __shfl_xor_sync(~0u, rs0, 1); rs0 += __shfl_xor_sync(~0u, rs0, 2);
        rs1 += __shfl_xor_sync(~0u, rs1, 1); rs1 += __shfl_xor_sync(~0u, rs1, 2);
        l0 = l0 * al0 + rs0; l1 = l1 * al1 + rs1; mr0 = mn0; mr1 = mn1;
#pragma unroll
        for (int ni = 0; ni < 4; ni++) {
            oacc[ni][0] *= al0; oacc[ni][1] *= al0; oacc[ni][2] *= al1; oacc[ni][3] *= al1;
        }
        __syncwarp();
#pragma unroll
        for (int kk = 0; kk < 64; kk += 8) {
            unsigned a[4] = { sm.Ps[wm + g][kk + t], sm.Ps[wm + g + 8][kk + t],
                              sm.Ps[wm + g][kk + t + 4], sm.Ps[wm + g + 8][kk + t + 4] };
#pragma unroll
            for (int ni = 0; ni < 4; ni++) {
                unsigned bf[2] = { sm.Vs[cb][kk + t][ni * 8 + g],
                                   sm.Vs[cb][kk + t + 4][ni * 8 + g] };
                mma8(oacc[ni], a, bf);
            }
        }
    }
    float il0 = __fdividef(1.f, l0), il1 = __fdividef(1.f, l1);
#pragma unroll
    for (int ni = 0; ni < 4; ni++) {
        int col = ni * 8 + 2 * t;
        *(float2*)&g_o[((size_t)bh * NT + qi0) * ND + col] =
            make_float2(__uint_as_float(f2tf(oacc[ni][0] * il0)),
                        __uint_as_float(f2tf(oacc[ni][1] * il0)));
        *(float2*)&g_o[((size_t)bh * NT + qi1) * ND + col] =
            make_float2(__uint_as_float(f2tf(oacc[ni][2] * il1)),
                        __uint_as_float(f2tf(oacc[ni][3] * il1)));
    }
    if (t == 0) {
        g_m[(size_t)bh * NT + qi0] = mr0; g_l[(size_t)bh * NT + qi0] = l0;
        g_m[(size_t)bh * NT + qi1] = mr1; g_l[(size_t)bh * NT + qi1] = l1;
    }
}

// ---------------------------------------------------------------------------
// avg_probs: per (b, 64-q, 64-k) tile loop all 16 heads, cp.async pipelined.
// 8 warps: warp w -> rows (w>>1)*16, cols (w&1)*32.
// Grid (NT/64, NT/64, NB), 256 threads.
// ---------------------------------------------------------------------------
__global__ __launch_bounds__(256,2) void attn_avg(float* __restrict__ avg) {
    __shared__ unsigned Qs[2][64][36];
    __shared__ unsigned Ks[2][64][36];
    int k0 = blockIdx.x * 64, q0 = blockIdx.y * 64, b = blockIdx.z;
    int tid = threadIdx.x, wid = tid >> 5, lane = tid & 31, g = lane >> 2, t = lane & 3;
    int wm = (wid >> 1) * 16, wn = (wid & 1) * 32;
    int qi0 = q0 + wm + g, qi1 = qi0 + 8;

    // prologue: head 0
    {
        int bh = b * NH;
#pragma unroll
        for (int i = 0; i < 2; i++) {
            int idx = tid + i * 256; int r = idx >> 3, c = (idx & 7) * 4;
            cpa16(&Qs[0][r][c], &g_q[((size_t)bh * NT + q0 + r) * ND + c]);
            cpa16(&Ks[0][r][c], &g_k[((size_t)bh * NT + k0 + r) * ND + c]);
        }
        cpcommit();
    }
    float acc[4][4] = {};
    int cb = 0;
    for (int h = 0; h < NH; h++, cb ^= 1) {
        int bh = b * NH + h;
        __syncthreads();
        if (h + 1 < NH) {
            int bh2 = bh + 1;
#pragma unroll
            for (int i = 0; i < 2; i++) {
                int idx = tid + i * 256; int r = idx >> 3, c = (idx & 7) * 4;
                cpa16(&Qs[cb^1][r][c], &g_q[((size_t)bh2 * NT + q0 + r) * ND + c]);
                cpa16(&Ks[cb^1][r][c], &g_k[((size_t)bh2 * NT + k0 + r) * ND + c]);
            }
            cpcommit(); cpwait<1>();
        } else cpwait<0>();
        __syncthreads();

        float sacc[4][4] = {};
#pragma unroll
        for (int kk = 0; kk < 32; kk += 8) {
            unsigned a[4] = { Qs[cb][wm + g][kk + t], Qs[cb][wm + g + 8][kk + t],
                              Qs[cb][wm + g][kk + t + 4], Qs[cb][wm + g + 8][kk + t + 4] };
#pragma unroll
            for (int ni = 0; ni < 4; ni++) {
                unsigned bf[2] = { Ks[cb][wn + ni * 8 + g][kk + t],
                                   Ks[cb][wn + ni * 8 + g][kk + t + 4] };
                mma8(sacc[ni], a, bf);
            }
        }
        float m0v = g_m[(size_t)bh * NT + qi0];
        float i0v = __fdividef(1.f, g_l[(size_t)bh * NT + qi0]);
        float m1v = g_m[(size_t)bh * NT + qi1];
        float i1v = __fdividef(1.f, g_l[(size_t)bh * NT + qi1]);
        float slope = exp2f(-(float)(h + 1) * (1.0f / 16.0f));
#pragma unroll
        for (int ni = 0; ni < 4; ni++) {
            float kj = (float)(k0 + wn + ni * 8 + 2 * t);
            acc[ni][0] += __expf(sacc[ni][0] * SCALE + slope * ((float)qi0 - kj) - m0v) * i0v;
            acc[ni][1] += __expf(sacc[ni][1] * SCALE + slope * ((float)qi0 - kj - 1.f) - m0v) * i0v;
            acc[ni][2] += __expf(sacc[ni][2] * SCALE + slope * ((float)qi1 - kj) - m1v) * i1v;
            acc[ni][3] += __expf(sacc[ni][3] * SCALE + slope * ((float)qi1 - kj - 1.f) - m1v) * i1v;
        }
    }
#pragma unroll
    for (int ni = 0; ni < 4; ni++) {
        int col = k0 + wn + ni * 8 + 2 * t;
        *(float2*)&avg[((size_t)b * NT + qi0) * NT + col] =
            make_float2(acc[ni][0] * 0.0625f, acc[ni][1] * 0.0625f);
        *(float2*)&avg[((size_t)b * NT + qi1) * NT + col] =
            make_float2(acc[ni][2] * 0.0625f, acc[ni][3] * 0.0625f);
    }
}

// ---------------------------------------------------------------------------
// Output projection, tf32 mma, cp.async double-buffered; A gathered from g_o
// (already tf32-rounded -> no cvt on A). Grid (BT/128, NC/64), 256 threads.
// ---------------------------------------------------------------------------
__global__ __launch_bounds__(256,2) void gemm_out(const float* __restrict__ Wo,
                                                  const float* __restrict__ bo,
                                                  float* __restrict__ out) {
    __shared__ float As[2][128][20];
    __shared__ float Bs[2][64][20];
    int m0 = blockIdx.x * 128, n0 = blockIdx.y * 64;
    int tid = threadIdx.x, wid = tid >> 5, lane = tid & 31, g = lane >> 2, t = lane & 3;
    int wm = (wid & 3) * 32, wn = (wid >> 2) * 32;

    // prologue k0=0
    {
#pragma unroll
        for (int i = 0; i < 2; i++) {
            int idx = tid + i * 256; int r = idx >> 2, c = (idx & 3) * 4;
            int m = m0 + r; int bi = m >> 11, tt = m & 2047;
            int h = c >> 5, d = c & 31;
            cpa16(&As[0][r][c], &g_o[((size_t)(bi * NH + h) * NT + tt) * ND + d]);
        }
        int r = tid >> 2, c = (tid & 3) * 4;
        cpa16(&Bs[0][r][c], &Wo[(size_t)(n0 + r) * NC + c]);
        cpcommit();
    }

    float acc[2][4][4] = {};
    int cb = 0;
    for (int k0 = 0; k0 < NC; k0 += 16, cb ^= 1) {
        __syncthreads();
        if (k0 + 16 < NC) {
            int kn = k0 + 16;
#pragma unroll
            for (int i = 0; i < 2; i++) {
                int idx = tid + i * 256; int r = idx >> 2, c = (idx & 3) * 4;
                int m = m0 + r; int bi = m >> 11, tt = m & 2047;
                int k = kn + c; int h = k >> 5, d = k & 31;
                cpa16(&As[cb^1][r][c], &g_o[((size_t)(bi * NH + h) * NT + tt) * ND + d]);
            }
            int r = tid >> 2, c = (tid & 3) * 4;
            cpa16(&Bs[cb^1][r][c], &Wo[(size_t)(n0 + r) * NC + kn + c]);
            cpcommit(); cpwait<1>();
        } else cpwait<0>();
        __syncthreads();
#pragma unroll
        for (int kk = 0; kk < 16; kk += 8) {
            unsigned a[2][4], b[4][2];
#pragma unroll
            for (int mi = 0; mi < 2; mi++) {
                int rb = wm + mi * 16;
                a[mi][0] = __float_as_uint(As[cb][rb + g][kk + t]);
                a[mi][1] = __float_as_uint(As[cb][rb + g + 8][kk + t]);
                a[mi][2] = __float_as_uint(As[cb][rb + g][kk + t + 4]);
                a[mi][3] = __float_as_uint(As[cb][rb + g + 8][kk + t + 4]);
            }
#pragma unroll
            for (int ni = 0; ni < 4; ni++) {
                b[ni][0] = f2tf(Bs[cb][wn + ni * 8 + g][kk + t]);
                b[ni][1] = f2tf(Bs[cb][wn + ni * 8 + g][kk + t + 4]);
            }
#pragma unroll
            for (int mi = 0; mi < 2; mi++)
#pragma unroll
                for (int ni = 0; ni < 4; ni++) mma8(acc[mi][ni], a[mi], b[ni]);
        }
    }
#pragma unroll
    for (int mi = 0; mi < 2; mi++) {
        int r0 = m0 + wm + mi * 16 + g;
        int r1 = r0 + 8;
#pragma unroll
        for (int ni = 0; ni < 4; ni++) {
            int n = n0 + wn + ni * 8 + 2 * t;
            float bb0 = bo[n], bb1 = bo[n + 1];
            *(float2*)&out[(size_t)r0 * NC + n] = make_float2(acc[mi][ni][0] + bb0, acc[mi][ni][1] + bb1);
            *(float2*)&out[(size_t)r1 * NC + n] = make_float2(acc[mi][ni][2] + bb0, acc[mi][ni][3] + bb1);
        }
    }
}

// ---------------------------------------------------------------------------
extern "C" void kernel_launch(void* const* d_in, const int* in_sizes, int n_in,
                              void* d_out, int out_size) {
    const float* x  = (const float*)d_in[0];
    const float* Wq = (const float*)d_in[1];
    const float* bq = (const float*)d_in[2];
    const float* Wk = (const float*)d_in[3];
    const float* bk = (const float*)d_in[4];
    const float* Wv = (const float*)d_in[5];
    const float* bv = (const float*)d_in[6];
    const float* Wo = (const float*)d_in[7];
    const float* bo = (const float*)d_in[8];

    float* out = (float*)d_out;                 // (B,T,C)
    float* avg = out + (size_t)NB*NT*NC;        // (B,T,T)

    cudaFuncSetAttribute(flash_attn, cudaFuncAttributeMaxDynamicSharedMemorySize,
                         (int)sizeof(FlashSmem));

    dim3 g1(BT/128, NC/64, 3);
    gemm_qkv<<<g1, 256>>>(x, Wq, bq, Wk, bk, Wv, bv);

    dim3 g2(NT/128, NH, NB);
    flash_attn<<<g2, 256, sizeof(FlashSmem)>>>();

    dim3 g3(NT/64, NT/64, NB);
    attn_avg<<<g3, 256>>>(avg);

    dim3 g4(BT/128, NC/64);
    gemm_out<<<g4, 256>>>(Wo, bo, out);
}

// round 6
// speedup vs baseline: 4.0920x; 1.1138x over previous
#include <cuda_runtime.h>

#define NB 2
#define NT 2048
#define NC 512
#define NH 16
#define ND 32
#define BT (NB*NT)          // 4096
#define SCALE 0.17677669529663687f          // 1/sqrt(32)
#define LOG2E 1.4426950408889634f
#define SCALE2 (SCALE * LOG2E)              // folded into Q at projection time

// Scratch (device globals). g_q holds tf32-rounded Q*SCALE2 with d-permuted
// layout; g_k tf32-rounded K d-permuted; g_v/g_o tf32-rounded, natural layout.
// g_m is the row max in log2 domain; g_l the linear sum of 2^().
__device__ float g_q[NB*NH*NT*ND];
__device__ float g_k[NB*NH*NT*ND];
__device__ float g_v[NB*NH*NT*ND];
__device__ float g_o[NB*NH*NT*ND];
__device__ float g_m[NB*NH*NT];
__device__ float g_l[NB*NH*NT];

__device__ __forceinline__ unsigned f2tf(float f) {
    unsigned u; asm("cvt.rna.tf32.f32 %0, %1;" : "=r"(u) : "f"(f)); return u;
}
__device__ __forceinline__ float ex2f(float x) {
    float y; asm("ex2.approx.f32 %0, %1;" : "=f"(y) : "f"(x)); return y;
}
// slot s of a k8 mma group lives at physical column 2*(s&3) + (s>>2)
__device__ __forceinline__ int dperm(int d) {
    return (d & 24) | ((d & 3) << 1) | ((d >> 2) & 1);
}

// D += A*B, m16n8k8 tf32.
__device__ __forceinline__ void mma8(float d[4], const unsigned a[4], const unsigned b[2]) {
    asm("mma.sync.aligned.m16n8k8.row.col.f32.tf32.tf32.f32 "
        "{%0,%1,%2,%3},{%4,%5,%6,%7},{%8,%9},{%0,%1,%2,%3};"
        : "+f"(d[0]), "+f"(d[1]), "+f"(d[2]), "+f"(d[3])
        : "r"(a[0]), "r"(a[1]), "r"(a[2]), "r"(a[3]), "r"(b[0]), "r"(b[1]));
}

__device__ __forceinline__ void cpa16(void* s, const void* g) {
    unsigned sa = (unsigned)__cvta_generic_to_shared(s);
    asm volatile("cp.async.cg.shared.global [%0], [%1], 16;" :: "r"(sa), "l"(g));
}
__device__ __forceinline__ void cpcommit() { asm volatile("cp.async.commit_group;"); }
template<int N> __device__ __forceinline__ void cpwait() {
    asm volatile("cp.async.wait_group %0;" :: "n"(N));
}

// ---------------------------------------------------------------------------
// Shared tile struct for both projection GEMMs (dynamic smem: 55,296 B)
// ---------------------------------------------------------------------------
struct __align__(16) GemmSmem {
    float As[2][128][36];
    float Bs[2][64][36];
};

// ---------------------------------------------------------------------------
// QKV projection, tf32 mma, K-step 32, cp.async double-buffered.
// Q: scaled by SCALE2, d-permuted.  K: d-permuted.  V: natural.
// Grid (BT/128, NC/64, 3), 256 threads.
// ---------------------------------------------------------------------------
__global__ __launch_bounds__(256,2) void gemm_qkv(const float* __restrict__ x,
    const float* __restrict__ Wq, const float* __restrict__ bq,
    const float* __restrict__ Wk, const float* __restrict__ bk,
    const float* __restrict__ Wv, const float* __restrict__ bv) {
    extern __shared__ char smraw[];
    GemmSmem& sm = *reinterpret_cast<GemmSmem*>(smraw);
    int sel = blockIdx.z;
    const float* W    = sel == 0 ? Wq : (sel == 1 ? Wk : Wv);
    const float* bias = sel == 0 ? bq : (sel == 1 ? bk : bv);
    float* outp       = sel == 0 ? g_q : (sel == 1 ? g_k : g_v);

    int m0 = blockIdx.x * 128, n0 = blockIdx.y * 64;
    int tid = threadIdx.x, wid = tid >> 5, lane = tid & 31, g = lane >> 2, t = lane & 3;
    int wm = (wid & 3) * 32, wn = (wid >> 2) * 32;

    // prologue: k-step 0 into buffer 0
    {
#pragma unroll
        for (int i = 0; i < 4; i++) {
            int idx = tid + i * 256; int r = idx >> 3, c = (idx & 7) * 4;
            cpa16(&sm.As[0][r][c], &x[(size_t)(m0 + r) * NC + c]);
        }
#pragma unroll
        for (int i = 0; i < 2; i++) {
            int idx = tid + i * 256; int r = idx >> 3, c = (idx & 7) * 4;
            cpa16(&sm.Bs[0][r][c], &W[(size_t)(n0 + r) * NC + c]);
        }
        cpcommit();
    }

    float acc[2][4][4] = {};
    int cb = 0;
    for (int k0 = 0; k0 < NC; k0 += 32, cb ^= 1) {
        __syncthreads();
        if (k0 + 32 < NC) {
            int kn = k0 + 32;
#pragma unroll
            for (int i = 0; i < 4; i++) {
                int idx = tid + i * 256; int r = idx >> 3, c = (idx & 7) * 4;
                cpa16(&sm.As[cb^1][r][c], &x[(size_t)(m0 + r) * NC + kn + c]);
            }
#pragma unroll
            for (int i = 0; i < 2; i++) {
                int idx = tid + i * 256; int r = idx >> 3, c = (idx & 7) * 4;
                cpa16(&sm.Bs[cb^1][r][c], &W[(size_t)(n0 + r) * NC + kn + c]);
            }
            cpcommit(); cpwait<1>();
        } else cpwait<0>();
        __syncthreads();
#pragma unroll
        for (int kk = 0; kk < 32; kk += 8) {
            unsigned a[2][4], b[4][2];
#pragma unroll
            for (int mi = 0; mi < 2; mi++) {
                int rb = wm + mi * 16;
                a[mi][0] = f2tf(sm.As[cb][rb + g][kk + t]);     a[mi][1] = f2tf(sm.As[cb][rb + g + 8][kk + t]);
                a[mi][2] = f2tf(sm.As[cb][rb + g][kk + t + 4]); a[mi][3] = f2tf(sm.As[cb][rb + g + 8][kk + t + 4]);
            }
#pragma unroll
            for (int ni = 0; ni < 4; ni++) {
                b[ni][0] = f2tf(sm.Bs[cb][wn + ni * 8 + g][kk + t]);
                b[ni][1] = f2tf(sm.Bs[cb][wn + ni * 8 + g][kk + t + 4]);
            }
#pragma unroll
            for (int mi = 0; mi < 2; mi++)
#pragma unroll
                for (int ni = 0; ni < 4; ni++) mma8(acc[mi][ni], a[mi], b[ni]);
        }
    }
#pragma unroll
    for (int mi = 0; mi < 2; mi++) {
        int r0 = m0 + wm + mi * 16 + g;
        int r1 = r0 + 8;
        int b0i = r0 >> 11, t0 = r0 & 2047;
        int b1i = r1 >> 11, t1 = r1 & 2047;
#pragma unroll
        for (int ni = 0; ni < 4; ni++) {
            int n = n0 + wn + ni * 8 + 2 * t;
            int h = n >> 5, d = n & 31;
            float bb0 = bias[n], bb1 = bias[n + 1];
            float v00 = acc[mi][ni][0] + bb0, v01 = acc[mi][ni][1] + bb1;
            float v10 = acc[mi][ni][2] + bb0, v11 = acc[mi][ni][3] + bb1;
            size_t base0 = ((size_t)(b0i * NH + h) * NT + t0) * ND;
            size_t base1 = ((size_t)(b1i * NH + h) * NT + t1) * ND;
            if (sel == 2) {
                *(float2*)&outp[base0 + d] = make_float2(__uint_as_float(f2tf(v00)),
                                                         __uint_as_float(f2tf(v01)));
                *(float2*)&outp[base1 + d] = make_float2(__uint_as_float(f2tf(v10)),
                                                         __uint_as_float(f2tf(v11)));
            } else {
                if (sel == 0) { v00 *= SCALE2; v01 *= SCALE2; v10 *= SCALE2; v11 *= SCALE2; }
                int p0 = dperm(d), p1 = dperm(d + 1);
                outp[base0 + p0] = __uint_as_float(f2tf(v00));
                outp[base0 + p1] = __uint_as_float(f2tf(v01));
                outp[base1 + p0] = __uint_as_float(f2tf(v10));
                outp[base1 + p1] = __uint_as_float(f2tf(v11));
            }
        }
    }
}

// ---------------------------------------------------------------------------
// Fused flash attention, log2-domain softmax, paired 64-bit fragment loads.
// Grid (NT/128, NH, NB), 256 threads, dynamic smem.
// ---------------------------------------------------------------------------
struct __align__(16) FlashSmem {
    unsigned Qs[128][40];
    unsigned Ks[2][64][40];
    unsigned Vs[2][64][40];
    unsigned Ps[128][72];
};

__global__ __launch_bounds__(256,2) void flash_attn() {
    extern __shared__ char smraw[];
    FlashSmem& sm = *reinterpret_cast<FlashSmem*>(smraw);
    int q0 = blockIdx.x * 128, h = blockIdx.y, b = blockIdx.z;
    int bh = b * NH + h;
    int tid = threadIdx.x, wid = tid >> 5, lane = tid & 31, g = lane >> 2, t = lane & 3;
    int wm = wid * 16;
    const float* qp = g_q + (size_t)bh * NT * ND;
    const float* kp = g_k + (size_t)bh * NT * ND;
    const float* vp = g_v + (size_t)bh * NT * ND;

    // Q tile + stage-0 K/V via cp.async (one commit group)
#pragma unroll
    for (int i = 0; i < 4; i++) {
        int idx = tid + i * 256; int r = idx >> 3, c = (idx & 7) * 4;
        cpa16(&sm.Qs[r][c], &qp[(size_t)(q0 + r) * ND + c]);
    }
#pragma unroll
    for (int i = 0; i < 2; i++) {
        int idx = tid + i * 256; int r = idx >> 3, c = (idx & 7) * 4;
        cpa16(&sm.Ks[0][r][c], &kp[(size_t)r * ND + c]);
        cpa16(&sm.Vs[0][r][c], &vp[(size_t)r * ND + c]);
    }
    cpcommit();

    float slope2 = exp2f(-(float)(h + 1) * (1.0f / 16.0f)) * LOG2E;
    float mr0 = -1e30f, mr1 = -1e30f, l0 = 0.f, l1 = 0.f;
    float oacc[4][4] = {};
    int qi0 = q0 + wm + g, qi1 = qi0 + 8;
    // per-thread column offsets (2t + ni*8), scaled by slope2
    float skc[8];
#pragma unroll
    for (int ni = 0; ni < 8; ni++) skc[ni] = slope2 * (float)(ni * 8 + 2 * t);
    int cb = 0;

    for (int kt = 0; kt < NT; kt += 64, cb ^= 1) {
        __syncthreads();
        if (kt + 64 < NT) {
            const float* kp2 = kp + (size_t)(kt + 64) * ND;
            const float* vp2 = vp + (size_t)(kt + 64) * ND;
#pragma unroll
            for (int i = 0; i < 2; i++) {
                int idx = tid + i * 256; int r = idx >> 3, c = (idx & 7) * 4;
                cpa16(&sm.Ks[cb^1][r][c], &kp2[(size_t)r * ND + c]);
                cpa16(&sm.Vs[cb^1][r][c], &vp2[(size_t)r * ND + c]);
            }
            cpcommit(); cpwait<1>();
        } else cpwait<0>();
        __syncthreads();

        float sacc[8][4] = {};
#pragma unroll
        for (int kk = 0; kk < 32; kk += 8) {
            uint2 u0 = *(const uint2*)&sm.Qs[wm + g][kk + 2 * t];
            uint2 u1 = *(const uint2*)&sm.Qs[wm + g + 8][kk + 2 * t];
            unsigned a[4] = { u0.x, u1.x, u0.y, u1.y };
#pragma unroll
            for (int ni = 0; ni < 8; ni++) {
                uint2 bv = *(const uint2*)&sm.Ks[cb][ni * 8 + g][kk + 2 * t];
                unsigned bf[2] = { bv.x, bv.y };
                mma8(sacc[ni], a, bf);
            }
        }
        // log2-domain ALiBi add (Q already carries SCALE*log2e)
        float base0 = slope2 * (float)(qi0 - kt);
        float base1 = slope2 * (float)(qi1 - kt);
        float rmax0 = -1e30f, rmax1 = -1e30f;
#pragma unroll
        for (int ni = 0; ni < 8; ni++) {
            float c00 = base0 - skc[ni], c01 = c00 - slope2;
            float c10 = base1 - skc[ni], c11 = c10 - slope2;
            sacc[ni][0] += c00; sacc[ni][1] += c01;
            sacc[ni][2] += c10; sacc[ni][3] += c11;
            rmax0 = fmaxf(rmax0, fmaxf(sacc[ni][0], sacc[ni][1]));
            rmax1 = fmaxf(rmax1, fmaxf(sacc[ni][2], sacc[ni][3]));
        }
        rmax0 = fmaxf(rmax0, __shfl_xor_sync(~0u, rmax0, 1));
        rmax0 = fmaxf(rmax0, __shfl_xor_sync(~0u, rmax0, 2));
        rmax1 = fmaxf(rmax1, __shfl_xor_sync(~0u, rmax1, 1));
        rmax1 = fmaxf(rmax1, __shfl_xor_sync(~0u, rmax1, 2));
        float mn0 = fmaxf(mr0, rmax0), mn1 = fmaxf(mr1, rmax1);
        float al0 = ex2f(mr0 - mn0), al1 = ex2f(mr1 - mn1);
        float rs0 = 0.f, rs1 = 0.f;
#pragma unroll
        for (int ni = 0; ni < 8; ni++) {
            float p0 = ex2f(sacc[ni][0] - mn0);
            float p1 = ex2f(sacc[ni][1] - mn0);
            float p2 = ex2f(sacc[ni][2] - mn1);
            float p3 = ex2f(sacc[ni][3] - mn1);
            rs0 += p0 + p1; rs1 += p2 + p3;
            int col = ni * 8 + 2 * t;
            *(uint2*)&sm.Ps[wm + g][col]     = make_uint2(f2tf(p0), f2tf(p1));
            *(uint2*)&sm.Ps[wm + g + 8][col] = make_uint2(f2tf(p2), f2tf(p3));
        }
        rs0 += __shfl_xor_sync(~0u, rs0, 1); rs0 += __shfl_xor_sync(~0u, rs0, 2);
        rs1 += __shfl_xor_sync(~0u, rs1, 1); rs1 += __shfl_xor_sync(~0u, rs1, 2);
        l0 = l0 * al0 + rs0; l1 = l1 * al1 + rs1; mr0 = mn0; mr1 = mn1;
#pragma unroll
        for (int ni = 0; ni < 4; ni++) {
            oacc[ni][0] *= al0; oacc[ni][1] *= al0; oacc[ni][2] *= al1; oacc[ni][3] *= al1;
        }
        __syncwarp();
#pragma unroll
        for (int kk = 0; kk < 64; kk += 8) {
            unsigned a[4] = { sm.Ps[wm + g][kk + t], sm.Ps[wm + g + 8][kk + t],
                              sm.Ps[wm + g][kk + t + 4], sm.Ps[wm + g + 8][kk + t + 4] };
#pragma unroll
            for (int ni = 0; ni < 4; ni++) {
                unsigned bf[2] = { sm.Vs[cb][kk + t][ni * 8 + g],
                                   sm.Vs[cb][kk + t + 4][ni * 8 + g] };
                mma8(oacc[ni], a, bf);
            }
        }
    }
    float il0 = __fdividef(1.f, l0), il1 = __fdividef(1.f, l1);
#pragma unroll
    for (int ni = 0; ni < 4; ni++) {
        int col = ni * 8 + 2 * t;
        *(float2*)&g_o[((size_t)bh * NT + qi0) * ND + col] =
            make_float2(__uint_as_float(f2tf(oacc[ni][0] * il0)),
                        __uint_as_float(f2tf(oacc[ni][1] * il0)));
        *(float2*)&g_o[((size_t)bh * NT + qi1) * ND + col] =
            make_float2(__uint_as_float(f2tf(oacc[ni][2] * il1)),
                        __uint_as_float(f2tf(oacc[ni][3] * il1)));
    }
    if (t == 0) {
        g_m[(size_t)bh * NT + qi0] = mr0; g_l[(size_t)bh * NT + qi0] = l0;
        g_m[(size_t)bh * NT + qi1] = mr1; g_l[(size_t)bh * NT + qi1] = l1;
    }
}

// ---------------------------------------------------------------------------
// avg_probs, log2-domain, paired 64-bit fragment loads.
// Grid (NT/64, NT/64, NB), 256 threads; 8 warps -> 16x32 sub-tiles.
// ---------------------------------------------------------------------------
__global__ __launch_bounds__(256,2) void attn_avg(float* __restrict__ avg) {
    __shared__ __align__(16) unsigned Qs[2][64][40];
    __shared__ __align__(16) unsigned Ks[2][64][40];
    int k0 = blockIdx.x * 64, q0 = blockIdx.y * 64, b = blockIdx.z;
    int tid = threadIdx.x, wid = tid >> 5, lane = tid & 31, g = lane >> 2, t = lane & 3;
    int wm = (wid >> 1) * 16, wn = (wid & 1) * 32;
    int qi0 = q0 + wm + g, qi1 = qi0 + 8;
    float kj0f = (float)(k0 + wn + 2 * t);

    // prologue: head 0
    {
        int bh = b * NH;
#pragma unroll
        for (int i = 0; i < 2; i++) {
            int idx = tid + i * 256; int r = idx >> 3, c = (idx & 7) * 4;
            cpa16(&Qs[0][r][c], &g_q[((size_t)bh * NT + q0 + r) * ND + c]);
            cpa16(&Ks[0][r][c], &g_k[((size_t)bh * NT + k0 + r) * ND + c]);
        }
        cpcommit();
    }
    float acc[4][4] = {};
    int cb = 0;
    for (int h = 0; h < NH; h++, cb ^= 1) {
        int bh = b * NH + h;
        __syncthreads();
        if (h + 1 < NH) {
            int bh2 = bh + 1;
#pragma unroll
            for (int i = 0; i < 2; i++) {
                int idx = tid + i * 256; int r = idx >> 3, c = (idx & 7) * 4;
                cpa16(&Qs[cb^1][r][c], &g_q[((size_t)bh2 * NT + q0 + r) * ND + c]);
                cpa16(&Ks[cb^1][r][c], &g_k[((size_t)bh2 * NT + k0 + r) * ND + c]);
            }
            cpcommit(); cpwait<1>();
        } else cpwait<0>();
        __syncthreads();

        float sacc[4][4] = {};
#pragma unroll
        for (int kk = 0; kk < 32; kk += 8) {
            uint2 u0 = *(const uint2*)&Qs[cb][wm + g][kk + 2 * t];
            uint2 u1 = *(const uint2*)&Qs[cb][wm + g + 8][kk + 2 * t];
            unsigned a[4] = { u0.x, u1.x, u0.y, u1.y };
#pragma unroll
            for (int ni = 0; ni < 4; ni++) {
                uint2 bv = *(const uint2*)&Ks[cb][wn + ni * 8 + g][kk + 2 * t];
                unsigned bf[2] = { bv.x, bv.y };
                mma8(sacc[ni], a, bf);
            }
        }
        float m0v = g_m[(size_t)bh * NT + qi0];
        float i0v = __fdividef(1.f, g_l[(size_t)bh * NT + qi0]);
        float m1v = g_m[(size_t)bh * NT + qi1];
        float i1v = __fdividef(1.f, g_l[(size_t)bh * NT + qi1]);
        float slope2 = exp2f(-(float)(h + 1) * (1.0f / 16.0f)) * LOG2E;
        float f0 = slope2 * (float)qi0 - m0v;
        float f1 = slope2 * (float)qi1 - m1v;
#pragma unroll
        for (int ni = 0; ni < 4; ni++) {
            float kjn = kj0f + (float)(ni * 8);
            float e00 = fmaf(-slope2, kjn, f0), e01 = e00 - slope2;
            float e10 = fmaf(-slope2, kjn, f1), e11 = e10 - slope2;
            acc[ni][0] += ex2f(sacc[ni][0] + e00) * i0v;
            acc[ni][1] += ex2f(sacc[ni][1] + e01) * i0v;
            acc[ni][2] += ex2f(sacc[ni][2] + e10) * i1v;
            acc[ni][3] += ex2f(sacc[ni][3] + e11) * i1v;
        }
    }
#pragma unroll
    for (int ni = 0; ni < 4; ni++) {
        int col = k0 + wn + ni * 8 + 2 * t;
        *(float2*)&avg[((size_t)b * NT + qi0) * NT + col] =
            make_float2(acc[ni][0] * 0.0625f, acc[ni][1] * 0.0625f);
        *(float2*)&avg[((size_t)b * NT + qi1) * NT + col] =
            make_float2(acc[ni][2] * 0.0625f, acc[ni][3] * 0.0625f);
    }
}

// ---------------------------------------------------------------------------
// Output projection, tf32 mma, K-step 32, cp.async double-buffered; A gathered
// from g_o (tf32-clean, natural layout). Grid (BT/128, NC/64), 256 threads.
// ---------------------------------------------------------------------------
__global__ __launch_bounds__(256,2) void gemm_out(const float* __restrict__ Wo,
                                                  const float* __restrict__ bo,
                                                  float* __restrict__ out) {
    extern __shared__ char smraw[];
    GemmSmem& sm = *reinterpret_cast<GemmSmem*>(smraw);
    int m0 = blockIdx.x * 128, n0 = blockIdx.y * 64;
    int tid = threadIdx.x, wid = tid >> 5, lane = tid & 31, g = lane >> 2, t = lane & 3;
    int wm = (wid & 3) * 32, wn = (wid >> 2) * 32;

    // prologue k0=0 (A k-cols 0..31 = h0 d0..31 -> contiguous in g_o)
    {
#pragma unroll
        for (int i = 0; i < 4; i++) {
            int idx = tid + i * 256; int r = idx >> 3, c = (idx & 7) * 4;
            int m = m0 + r; int bi = m >> 11, tt = m & 2047;
            cpa16(&sm.As[0][r][c], &g_o[((size_t)(bi * NH) * NT + tt) * ND + c]);
        }
#pragma unroll
        for (int i = 0; i < 2; i++) {
            int idx = tid + i * 256; int r = idx >> 3, c = (idx & 7) * 4;
            cpa16(&sm.Bs[0][r][c], &Wo[(size_t)(n0 + r) * NC + c]);
        }
        cpcommit();
    }

    float acc[2][4][4] = {};
    int cb = 0;
    for (int k0 = 0; k0 < NC; k0 += 32, cb ^= 1) {
        __syncthreads();
        if (k0 + 32 < NC) {
            int kn = k0 + 32;
            int hh = kn >> 5;   // k-step of 32 == exactly one head
#pragma unroll
            for (int i = 0; i < 4; i++) {
                int idx = tid + i * 256; int r = idx >> 3, c = (idx & 7) * 4;
                int m = m0 + r; int bi = m >> 11, tt = m & 2047;
                cpa16(&sm.As[cb^1][r][c], &g_o[((size_t)(bi * NH + hh) * NT + tt) * ND + c]);
            }
#pragma unroll
            for (int i = 0; i < 2; i++) {
                int idx = tid + i * 256; int r = idx >> 3, c = (idx & 7) * 4;
                cpa16(&sm.Bs[cb^1][r][c], &Wo[(size_t)(n0 + r) * NC + kn + c]);
            }
            cpcommit(); cpwait<1>();
        } else cpwait<0>();
        __syncthreads();
#pragma unroll
        for (int kk = 0; kk < 32; kk += 8) {
            unsigned a[2][4], b[4][2];
#pragma unroll
            for (int mi = 0; mi < 2; mi++) {
                int rb = wm + mi * 16;
                a[mi][0] = __float_as_uint(sm.As[cb][rb + g][kk + t]);
                a[mi][1] = __float_as_uint(sm.As[cb][rb + g + 8][kk + t]);
                a[mi][2] = __float_as_uint(sm.As[cb][rb + g][kk + t + 4]);
                a[mi][3] = __float_as_uint(sm.As[cb][rb + g + 8][kk + t + 4]);
            }
#pragma unroll
            for (int ni = 0; ni < 4; ni++) {
                b[ni][0] = f2tf(sm.Bs[cb][wn + ni * 8 + g][kk + t]);
                b[ni][1] = f2tf(sm.Bs[cb][wn + ni * 8 + g][kk + t + 4]);
            }
#pragma unroll
            for (int mi = 0; mi < 2; mi++)
#pragma unroll
                for (int ni = 0; ni < 4; ni++) mma8(acc[mi][ni], a[mi], b[ni]);
        }
    }
#pragma unroll
    for (int mi = 0; mi < 2; mi++) {
        int r0 = m0 + wm + mi * 16 + g;
        int r1 = r0 + 8;
#pragma unroll
        for (int ni = 0; ni < 4; ni++) {
            int n = n0 + wn + ni * 8 + 2 * t;
            float bb0 = bo[n], bb1 = bo[n + 1];
            *(float2*)&out[(size_t)r0 * NC + n] = make_float2(acc[mi][ni][0] + bb0, acc[mi][ni][1] + bb1);
            *(float2*)&out[(size_t)r1 * NC + n] = make_float2(acc[mi][ni][2] + bb0, acc[mi][ni][3] + bb1);
        }
    }
}

// ---------------------------------------------------------------------------
extern "C" void kernel_launch(void* const* d_in, const int* in_sizes, int n_in,
                              void* d_out, int out_size) {
    const float* x  = (const float*)d_in[0];
    const float* Wq = (const float*)d_in[1];
    const float* bq = (const float*)d_in[2];
    const float* Wk = (const float*)d_in[3];
    const float* bk = (const float*)d_in[4];
    const float* Wv = (const float*)d_in[5];
    const float* bv = (const float*)d_in[6];
    const float* Wo = (const float*)d_in[7];
    const float* bo = (const float*)d_in[8];

    float* out = (float*)d_out;                 // (B,T,C)
    float* avg = out + (size_t)NB*NT*NC;        // (B,T,T)

    cudaFuncSetAttribute(gemm_qkv, cudaFuncAttributeMaxDynamicSharedMemorySize,
                         (int)sizeof(GemmSmem));
    cudaFuncSetAttribute(flash_attn, cudaFuncAttributeMaxDynamicSharedMemorySize,
                         (int)sizeof(FlashSmem));
    cudaFuncSetAttribute(gemm_out, cudaFuncAttributeMaxDynamicSharedMemorySize,
                         (int)sizeof(GemmSmem));

    dim3 g1(BT/128, NC/64, 3);
    gemm_qkv<<<g1, 256, sizeof(GemmSmem)>>>(x, Wq, bq, Wk, bk, Wv, bv);

    dim3 g2(NT/128, NH, NB);
    flash_attn<<<g2, 256, sizeof(FlashSmem)>>>();

    dim3 g3(NT/64, NT/64, NB);
    attn_avg<<<g3, 256>>>(avg);

    dim3 g4(BT/128, NC/64);
    gemm_out<<<g4, 256, sizeof(GemmSmem)>>>(Wo, bo, out);
}